// round 4
// baseline (speedup 1.0000x reference)
#include <cuda_runtime.h>
#include <cstdint>
#include <cstddef>

#define NB 16
#define HH 256
#define WW 256
#define NPIX (NB * HH * WW)        // 1,048,576 pixels (per-channel BN count)
#define C1 128
#define C2 64

// ---------------- static device scratch (no allocations allowed) ----------------
__device__ uint32_t           g_xbits[NB * HH * (WW / 32)];   // packed sign(x), 128KB
__device__ unsigned long long g_wb1[C1];                      // 49-bit weight signs, layer1
__device__ uint4              g_wb2[C2];                      // 128-bit weight signs, layer2
__device__ unsigned long long g_s1[C1];                       // sum v1 (2's complement)
__device__ unsigned long long g_q1[C1];                       // sum v1^2
__device__ int                g_lo[C1];                       // sign threshold interval lo
__device__ int                g_wd[C1];                       // interval width (hi-lo)
__device__ unsigned long long g_sk[C2];                       // sum k
__device__ unsigned long long g_qk[C2];                       // sum k^2
__device__ float              g_P[C2], g_Q[C2];               // h2 = lrelu(P*k + Q)
__device__ unsigned char      g_k2[(size_t)NB * C2 * HH * WW];// 64MB layer2 popcounts

// ---------------- prep: pack weight signs + zero stats ----------------
__global__ void k_prep(const float* __restrict__ w1, const float* __restrict__ w2) {
    int t = threadIdx.x;
    if (t < C1) {
        unsigned long long b = 0ull;
        #pragma unroll
        for (int j = 0; j < 49; j++)
            if (w1[t * 49 + j] >= 0.f) b |= (1ull << j);
        g_wb1[t] = b;
        g_s1[t] = 0ull;
        g_q1[t] = 0ull;
    }
    if (t < C2) {
        uint32_t w[4];
        #pragma unroll
        for (int q = 0; q < 4; q++) {
            uint32_t b = 0u;
            #pragma unroll
            for (int j = 0; j < 32; j++)
                if (w2[t * 128 + q * 32 + j] >= 0.f) b |= (1u << j);
            w[q] = b;
        }
        g_wb2[t] = make_uint4(w[0], w[1], w[2], w[3]);
        g_sk[t] = 0ull;
        g_qk[t] = 0ull;
    }
}

// ---------------- pack sign(x) into bitmap ----------------
__global__ void k_packx(const float* __restrict__ x) {
    int idx = blockIdx.x * 256 + threadIdx.x;
    unsigned b = __ballot_sync(0xFFFFFFFFu, x[idx] >= 0.f);
    if ((threadIdx.x & 31) == 0) g_xbits[idx >> 5] = b;
}

// ---------------- 7x7 window of sign bits + validity mask ----------------
__device__ __forceinline__ void build_window(int n, int y, int x,
                                             unsigned long long& win,
                                             unsigned long long& msk) {
    const uint32_t* rowbase = g_xbits + (n << 11);
    uint32_t colmask = 0x7Fu;
    if (x < 3)   colmask &= (0x7Fu << (3 - x));
    if (x > 252) colmask &= (0x7Fu >> (x - 252));
    colmask &= 0x7Fu;
    int base = x - 3;
    int wi = (base >= 0) ? (base >> 5) : -1;
    int sh = base & 31;
    win = 0ull; msk = 0ull;
    #pragma unroll
    for (int r = 0; r < 7; r++) {
        int yy = y + r - 3;
        if (yy >= 0 && yy < HH) {
            const uint32_t* rw = rowbase + (yy << 3);
            uint32_t w0 = (wi >= 0) ? rw[wi] : 0u;
            uint32_t w1 = (wi < 7) ? rw[wi + 1] : 0u;
            uint32_t bits = __funnelshift_r(w0, w1, sh) & colmask;
            win |= (unsigned long long)bits << (7 * r);
            msk |= (unsigned long long)colmask << (7 * r);
        }
    }
}

// ---------------- pass 1: layer1 conv -> per-channel integer stats ----------------
__global__ void k_conv1_stats() {
    __shared__ unsigned long long s_wb[C1];
    __shared__ int s_sum[C1];
    __shared__ int s_sq[C1];
    int t = threadIdx.x;
    if (t < C1) { s_wb[t] = g_wb1[t]; s_sum[t] = 0; s_sq[t] = 0; }
    __syncthreads();

    int p = blockIdx.x * 256 + t;
    int n = p >> 16;
    int rem = p & 65535;
    int y = rem >> 8;
    int x = rem & 255;
    unsigned long long win, msk;
    build_window(n, y, x, win, msk);
    int inb = __popcll(msk);
    int lane = t & 31;

    #pragma unroll 8
    for (int c = 0; c < C1; c++) {
        int dis = __popcll((win ^ s_wb[c]) & msk);
        int v = inb - 2 * dis;
        int s  = __reduce_add_sync(0xFFFFFFFFu, v);
        int s2 = __reduce_add_sync(0xFFFFFFFFu, v * v);
        if (lane == 0) { atomicAdd(&s_sum[c], s); atomicAdd(&s_sq[c], s2); }
    }
    __syncthreads();
    if (t < C1) {
        atomicAdd(&g_s1[t], (unsigned long long)(long long)s_sum[t]);
        atomicAdd(&g_q1[t], (unsigned long long)(long long)s_sq[t]);
    }
}

// ---------------- finalize BN1 -> integer sign-threshold interval on v ----------------
__global__ void k_fin1(const float* __restrict__ g1, const float* __restrict__ b1) {
    int c = threadIdx.x;
    if (c >= C1) return;
    double N = (double)NPIX;
    double S1 = (double)(long long)g_s1[c];
    double S2 = (double)g_q1[c];
    double mean = S1 / N;
    double var  = S2 / N - mean * mean;
    float meanf = (float)mean;
    float invf  = g1[c] * rsqrtf((float)var + 1e-5f);
    float beta  = b1[c];
    int lo = 100, hi = -100;
    bool any = false;
    for (int v = -49; v <= 49; v++) {
        float h = ((float)v - meanf) * invf + beta;
        if (h >= 0.f) { if (!any) { lo = v; any = true; } hi = v; }
    }
    if (!any) { g_lo[c] = 100; g_wd[c] = 0; }
    else      { g_lo[c] = lo;  g_wd[c] = hi - lo; }
}

// ---------------- pass 3: layer1 signs -> layer2 1x1 binary conv (store k) -----------
__global__ void k_sign_conv2() {
    __shared__ unsigned long long s_wb[C1];
    __shared__ int s_lo[C1];
    __shared__ int s_wd[C1];
    __shared__ uint4 s_w2[C2];
    int t = threadIdx.x;
    if (t < C1) { s_wb[t] = g_wb1[t]; s_lo[t] = g_lo[t]; s_wd[t] = g_wd[t]; }
    if (t < C2) s_w2[t] = g_wb2[t];
    __syncthreads();

    int p = blockIdx.x * 256 + t;
    int n = p >> 16;
    int rem = p & 65535;
    int y = rem >> 8;
    int x = rem & 255;
    unsigned long long win, msk;
    build_window(n, y, x, win, msk);
    int inb = __popcll(msk);

    uint32_t sw[4];
    #pragma unroll
    for (int w = 0; w < 4; w++) {
        uint32_t bits = 0u;
        #pragma unroll
        for (int j = 0; j < 32; j++) {
            int c = w * 32 + j;
            int dis = __popcll((win ^ s_wb[c]) & msk);
            int v = inb - 2 * dis;
            if ((unsigned)(v - s_lo[c]) <= (unsigned)s_wd[c]) bits |= (1u << j);
        }
        sw[w] = bits;
    }

    unsigned char* outb = g_k2 + ((size_t)n << 22) + rem;
    #pragma unroll 8
    for (int oc = 0; oc < C2; oc++) {
        uint4 wb = s_w2[oc];
        int k = __popc(sw[0] ^ wb.x) + __popc(sw[1] ^ wb.y) +
                __popc(sw[2] ^ wb.z) + __popc(sw[3] ^ wb.w);
        outb[(size_t)oc << 16] = (unsigned char)k;
    }
}

// ---------------- stats for BN2 from k bytes (dp4a) ----------------
__global__ void k_stats2() {
    int b = blockIdx.x;           // b = n*64 + c
    int c = b & 63;
    int t = threadIdx.x;
    const uint4* ptr = (const uint4*)(g_k2 + ((size_t)b << 16));
    unsigned s = 0u, s2 = 0u;
    #pragma unroll
    for (int i = 0; i < 16; i++) {
        uint4 v = ptr[t + i * 256];
        s  = __dp4a(v.x, 0x01010101u, s);  s2 = __dp4a(v.x, v.x, s2);
        s  = __dp4a(v.y, 0x01010101u, s);  s2 = __dp4a(v.y, v.y, s2);
        s  = __dp4a(v.z, 0x01010101u, s);  s2 = __dp4a(v.z, v.z, s2);
        s  = __dp4a(v.w, 0x01010101u, s);  s2 = __dp4a(v.w, v.w, s2);
    }
    s  = __reduce_add_sync(0xFFFFFFFFu, s);
    s2 = __reduce_add_sync(0xFFFFFFFFu, s2);
    __shared__ unsigned sh_s, sh_s2;
    if (t == 0) { sh_s = 0u; sh_s2 = 0u; }
    __syncthreads();
    if ((t & 31) == 0) { atomicAdd(&sh_s, s); atomicAdd(&sh_s2, s2); }
    __syncthreads();
    if (t == 0) {
        atomicAdd(&g_sk[c], (unsigned long long)sh_s);
        atomicAdd(&g_qk[c], (unsigned long long)sh_s2);
    }
}

// ---------------- finalize BN2 -> affine h2(k) = lrelu(P*k + Q) ----------------
__global__ void k_fin2(const float* __restrict__ g2, const float* __restrict__ b2) {
    int c = threadIdx.x;
    if (c >= C2) return;
    double N = (double)NPIX;
    double mk = (double)(long long)g_sk[c] / N;
    double qk = (double)g_qk[c] / N;
    double vark = qk - mk * mk;
    // v2 = 128 - 2k  ->  mean_v = 128 - 2*mk, var_v = 4*vark
    float meanv = (float)(128.0 - 2.0 * mk);
    float varv  = (float)(4.0 * vark);
    float inv   = g2[c] * rsqrtf(varv + 1e-5f);
    g_P[c] = -2.f * inv;
    g_Q[c] = (128.f - meanv) * inv + b2[c];
}

// ---------------- layer 3: fp32 5x5 conv, 64 ch -> 1 ch, smem-tiled ----------------
__global__ void k_conv3(const float* __restrict__ w3, float* __restrict__ out) {
    __shared__ float ht[8][36][36];     // 41,472 B
    __shared__ float w3s[C2 * 25];      //  6,400 B
    __shared__ float Ps[C2], Qs[C2];    //    512 B
    int tx = threadIdx.x;               // 0..7  (x-quad)
    int ty = threadIdx.y;               // 0..15 (y)
    int t = ty * 8 + tx;                // 0..127
    for (int i = t; i < C2 * 25; i += 128) w3s[i] = w3[i];
    if (t < C2) { Ps[t] = g_P[t]; Qs[t] = g_Q[t]; }

    int n = blockIdx.z;
    int X0 = blockIdx.x * 32;
    int Y0 = blockIdx.y * 32;
    const unsigned char* kbase = g_k2 + ((size_t)n << 22);

    float acc[2][4] = {{0.f, 0.f, 0.f, 0.f}, {0.f, 0.f, 0.f, 0.f}};

    for (int g = 0; g < 8; g++) {
        int c0 = g * 8;
        __syncthreads();
        // load 36x36 tile (with halo) for 8 channels, convert k -> h2
        for (int i = t; i < 1296; i += 128) {
            int yy = i / 36;
            int xx = i - yy * 36;
            int gy = Y0 - 2 + yy;
            int gx = X0 - 2 + xx;
            bool ok = (gy >= 0) && (gy < 256) && (gx >= 0) && (gx < 256);
            int off = gy * 256 + gx;
            #pragma unroll
            for (int c = 0; c < 8; c++) {
                float val = 0.f;
                if (ok) {
                    int k = kbase[((size_t)(c0 + c) << 16) + off];
                    float h = fmaf(Ps[c0 + c], (float)k, Qs[c0 + c]);
                    val = (h >= 0.f) ? h : 0.5f * h;
                }
                ht[c][yy][xx] = val;
            }
        }
        __syncthreads();

        #pragma unroll
        for (int c = 0; c < 8; c++) {
            #pragma unroll
            for (int ky = 0; ky < 5; ky++) {
                const float* wr = &w3s[(c0 + c) * 25 + ky * 5];
                float w0 = wr[0], w1 = wr[1], w2 = wr[2], w3v = wr[3], w4 = wr[4];
                #pragma unroll
                for (int ry = 0; ry < 2; ry++) {
                    int row = ty + 16 * ry + ky;
                    const float4* rp = (const float4*)&ht[c][row][tx * 4];
                    float4 a = rp[0];
                    float4 bq = rp[1];
                    float i0 = a.x, i1 = a.y, i2 = a.z, i3 = a.w;
                    float i4 = bq.x, i5 = bq.y, i6 = bq.z, i7 = bq.w;
                    acc[ry][0] = fmaf(i0, w0, fmaf(i1, w1, fmaf(i2, w2, fmaf(i3, w3v, fmaf(i4, w4, acc[ry][0])))));
                    acc[ry][1] = fmaf(i1, w0, fmaf(i2, w1, fmaf(i3, w2, fmaf(i4, w3v, fmaf(i5, w4, acc[ry][1])))));
                    acc[ry][2] = fmaf(i2, w0, fmaf(i3, w1, fmaf(i4, w2, fmaf(i5, w3v, fmaf(i6, w4, acc[ry][2])))));
                    acc[ry][3] = fmaf(i3, w0, fmaf(i4, w1, fmaf(i5, w2, fmaf(i6, w3v, fmaf(i7, w4, acc[ry][3])))));
                }
            }
        }
    }

    #pragma unroll
    for (int ry = 0; ry < 2; ry++) {
        int yo = Y0 + ty + 16 * ry;
        float4 v = make_float4(acc[ry][0], acc[ry][1], acc[ry][2], acc[ry][3]);
        *(float4*)&out[(n << 16) + yo * 256 + X0 + tx * 4] = v;
    }
}

// ---------------- launch ----------------
extern "C" void kernel_launch(void* const* d_in, const int* in_sizes, int n_in,
                              void* d_out, int out_size) {
    const float* x  = (const float*)d_in[0];
    const float* w1 = (const float*)d_in[1];
    const float* g1 = (const float*)d_in[2];
    const float* b1 = (const float*)d_in[3];
    const float* w2 = (const float*)d_in[4];
    const float* g2 = (const float*)d_in[5];
    const float* b2 = (const float*)d_in[6];
    const float* w3 = (const float*)d_in[7];
    float* out = (float*)d_out;

    k_prep<<<1, 256>>>(w1, w2);
    k_packx<<<NPIX / 256, 256>>>(x);
    k_conv1_stats<<<NPIX / 256, 256>>>();
    k_fin1<<<1, 128>>>(g1, b1);
    k_sign_conv2<<<NPIX / 256, 256>>>();
    k_stats2<<<NB * C2, 256>>>();
    k_fin2<<<1, 64>>>(g2, b2);
    k_conv3<<<dim3(8, 8, NB), dim3(8, 16)>>>(w3, out);
    (void)in_sizes; (void)n_in; (void)out_size;
}